// round 16
// baseline (speedup 1.0000x reference)
#include <cuda_runtime.h>
#include <cuda_fp16.h>
#include <cstdint>

// ---------------------------------------------------------------------------
// pointwise (Bahdanau additive) attention, fp32 via fp16 mma.sync HMMA
// B=32, T=2048, D=512, U=512
// out layout: [0, B*D) = context ; [B*D, B*D + B*T) = attn
// Round 15: R14 (in-register fp32->fp16 convert, hsplit deleted) with
// __launch_bounds__(256,1) — removes the register spill that sank R14.
// ---------------------------------------------------------------------------

#define CB 32
#define CT 2048
#define CD 512
#define CU 512

// scratch (allocation-free rule: __device__ globals)
__device__ float g_scores[CB * CT];
__device__ float g_dec_proj[CB * CU];
__device__ __half g_W1h[CU * CD];               // transposed: [u][k], fp16
__device__ __half g_Ah[(size_t)CB * CT * CD];   // h_enc fp16 (written by score)

// -------------------- PTX helpers --------------------
__device__ __forceinline__ uint32_t smem_u32(const void* p) {
    uint32_t a;
    asm("{ .reg .u64 t; cvta.to.shared.u64 t, %1; cvt.u32.u64 %0, t; }"
        : "=r"(a) : "l"(p));
    return a;
}
__device__ __forceinline__ void cp16(uint32_t dst, const void* src) {
    asm volatile("cp.async.cg.shared.global [%0], [%1], 16;"
                 :: "r"(dst), "l"(src) : "memory");
}
__device__ __forceinline__ uint32_t packh2(float a, float b) {
    uint32_t r;                                   // low=a, high=b
    asm("cvt.rn.f16x2.f32 %0, %1, %2;" : "=r"(r) : "f"(b), "f"(a));
    return r;
}
__device__ __forceinline__ float fast_tanh(float x) {
    float e;
    asm("ex2.approx.f32 %0, %1;" : "=f"(e) : "f"(x * 2.885390081777927f)); // e^(2x)
    float r;
    asm("rcp.approx.f32 %0, %1;" : "=f"(r) : "f"(e + 1.0f));
    return fmaf(-2.0f, r, 1.0f);
}

#define LDSM4(r, addr)                                                        \
    asm volatile("ldmatrix.sync.aligned.m8n8.x4.shared.b16 {%0,%1,%2,%3}, [%4];" \
                 : "=r"((r)[0]), "=r"((r)[1]), "=r"((r)[2]), "=r"((r)[3])     \
                 : "r"(addr))

#define MMAH(d, a, b0, b1)                                                    \
    asm volatile("mma.sync.aligned.m16n8k16.row.col.f32.f16.f16.f32 "         \
                 "{%0,%1,%2,%3}, {%4,%5,%6,%7}, {%8,%9}, {%0,%1,%2,%3};"      \
                 : "+f"((d)[0]), "+f"((d)[1]), "+f"((d)[2]), "+f"((d)[3])     \
                 : "r"((a)[0]), "r"((a)[1]), "r"((a)[2]), "r"((a)[3]),        \
                   "r"(b0), "r"(b1))

// -------------------- kernel 0: prep (w1conv + dec_proj + zero scores) -----
#define WC_BLOCKS 256
#define PREP_GRID (WC_BLOCKS + 64)

__global__ __launch_bounds__(256)
void fused_prep_kernel(const float* __restrict__ W1,
                       const float* __restrict__ h_dec,
                       const float* __restrict__ b1) {
    const int blk = blockIdx.x;
    const int tid = threadIdx.x;
    __shared__ float sh[32][33];            // w1conv transpose / prep hd

    if (blk < WC_BLOCKS) {
        const int u0 = (blk & 15) * 32, k0 = (blk >> 4) * 32;
        const int tx = tid & 31, ty = tid >> 5;
#pragma unroll
        for (int i = 0; i < 4; i++)
            sh[ty + i * 8][tx] = W1[(size_t)(k0 + ty + i * 8) * CU + u0 + tx];
        __syncthreads();
#pragma unroll
        for (int i = 0; i < 4; i++)
            g_W1h[(size_t)(u0 + ty + i * 8) * CD + k0 + tx] =
                __float2half_rn(sh[tx][ty + i * 8]);
    } else {
        const int id = blk - WC_BLOCKS;
        const int b = id >> 1, uh = id & 1;
        float* hd = &sh[0][0];              // 512 floats
        hd[tid] = h_dec[b * CD + tid];
        hd[tid + 256] = h_dec[b * CD + tid + 256];
        __syncthreads();
        const int u = uh * 256 + tid;
        float a0 = b1[u], a1 = 0.f, a2 = 0.f, a3 = 0.f;
        float a4 = 0.f, a5 = 0.f, a6 = 0.f, a7 = 0.f;
#pragma unroll 4
        for (int k = 0; k < CD; k += 8) {
            a0 += hd[k + 0] * W1[(size_t)(CD + k + 0) * CU + u];
            a1 += hd[k + 1] * W1[(size_t)(CD + k + 1) * CU + u];
            a2 += hd[k + 2] * W1[(size_t)(CD + k + 2) * CU + u];
            a3 += hd[k + 3] * W1[(size_t)(CD + k + 3) * CU + u];
            a4 += hd[k + 4] * W1[(size_t)(CD + k + 4) * CU + u];
            a5 += hd[k + 5] * W1[(size_t)(CD + k + 5) * CU + u];
            a6 += hd[k + 6] * W1[(size_t)(CD + k + 6) * CU + u];
            a7 += hd[k + 7] * W1[(size_t)(CD + k + 7) * CU + u];
        }
        g_dec_proj[b * CU + u] =
            ((a0 + a1) + (a2 + a3)) + ((a4 + a5) + (a6 + a7));
#pragma unroll
        for (int t = uh * 1024 + tid; t < uh * 1024 + 1024; t += 256)
            g_scores[b * CT + t] = 0.f;
    }
}

// -------------------- kernel 1: HMMA fp16 score GEMM (reg convert) ---------
// CTA tile: 128 t x 128 u, K=512 in 16 chunks of 32.
// smem: Ah fp16 x2 (8KB) | Bh fp16 x4 (8KB) | dp | w2  = 50176 B
#define SM_AHS  0
#define AH_SZ   8192
#define SM_BHS  16384
#define BH_SZ   8192
#define SM_DP   49152
#define SM_W2   49664
#define SM_TOT  50176

__global__ __launch_bounds__(256, 1)
void score_kernel(const float* __restrict__ h_enc, const float* __restrict__ W2) {
    extern __shared__ char smem[];
    const uint32_t sbase = smem_u32(smem);
    const int tid = threadIdx.x;
    const int wid = tid >> 5, lid = tid & 31;
    const int wm = wid >> 1, wn = wid & 1;
    const int b = blockIdx.y;
    const int ut = blockIdx.x & 3, tt = blockIdx.x >> 2;  // u-fastest: A L2-hot
    const int t0 = tt * 128, u0 = ut * 128;
    const size_t arow = (size_t)(b * CT + t0);

    // per-lane ldmatrix geometry (fp16 tiles, 64B rows, SW64-style XOR)
    const int rowAf = wm * 32 + (lid & 7) + ((lid >> 3) & 1) * 8;
    const int kselA = lid >> 4;
    const int rowBf = wn * 64 + (lid & 7) + (lid >> 4) * 8;
    const int kselB = (lid >> 3) & 1;

    uint32_t aoffs[2], boffs[2];
#pragma unroll
    for (int ks = 0; ks < 2; ks++) {
        aoffs[ks] = rowAf * 64 + (((ks * 2 + kselA) ^ ((rowAf >> 1) & 3)) << 4);
        boffs[ks] = rowBf * 64 + (((ks * 2 + kselB) ^ ((rowBf >> 1) & 3)) << 4);
    }

    // B cp.async geometry
    const int brB = tid >> 2, bchB = tid & 3;
    const uint32_t dB0 = brB * 64 + ((bchB ^ ((brB >> 1) & 3)) << 4);
    const __half* bP = g_W1h + (size_t)(u0 + brB) * CD + bchB * 8;

    // A register-convert geometry: thread owns (row = tid>>1, k-half = tid&1)
    const int crow = tid >> 1, chalf = tid & 1;
    const float* aP = h_enc + (arow + crow) * CD + chalf * 16;
    __half* gP = g_Ah + (arow + crow) * CD + chalf * 16;
    const uint32_t ds0 = crow * 64 + (((chalf * 2 + 0) ^ ((crow >> 1) & 3)) << 4);
    const uint32_t ds1 = crow * 64 + (((chalf * 2 + 1) ^ ((crow >> 1) & 3)) << 4);

    float* sdp = (float*)(smem + SM_DP);
    float* sw2 = (float*)(smem + SM_W2);
    if (tid < 128) {
        sdp[tid] = g_dec_proj[b * CU + u0 + tid];
        sw2[tid] = W2[u0 + tid];
    }

    float4 ra[4];
    auto ldgA = [&](int c) {
        const float* p = aP + c * 32;
        ra[0] = *(const float4*)(p + 0);
        ra[1] = *(const float4*)(p + 4);
        ra[2] = *(const float4*)(p + 8);
        ra[3] = *(const float4*)(p + 12);
    };
    auto cvtsts = [&](int c) {
        uint32_t uh0 = packh2(ra[0].x, ra[0].y), uh1 = packh2(ra[0].z, ra[0].w);
        uint32_t uh2 = packh2(ra[1].x, ra[1].y), uh3 = packh2(ra[1].z, ra[1].w);
        uint32_t uh4 = packh2(ra[2].x, ra[2].y), uh5 = packh2(ra[2].z, ra[2].w);
        uint32_t uh6 = packh2(ra[3].x, ra[3].y), uh7 = packh2(ra[3].z, ra[3].w);
        const uint32_t ahS = sbase + SM_AHS + (c & 1) * AH_SZ;
        asm volatile("st.shared.v4.b32 [%0], {%1,%2,%3,%4};"
                     :: "r"(ahS + ds0), "r"(uh0), "r"(uh1), "r"(uh2), "r"(uh3));
        asm volatile("st.shared.v4.b32 [%0], {%1,%2,%3,%4};"
                     :: "r"(ahS + ds1), "r"(uh4), "r"(uh5), "r"(uh6), "r"(uh7));
        if (ut == 0) {          // persist fp16 A for context (hidden under MMA)
            __half* gp = gP + c * 32;
            *(uint4*)gp = make_uint4(uh0, uh1, uh2, uh3);
            *(uint4*)(gp + 8) = make_uint4(uh4, uh5, uh6, uh7);
        }
    };
    auto cpB = [&](int c) {
        const uint32_t bhS = sbase + SM_BHS + (c & 3) * BH_SZ;
        const int k0 = c * 32;
        cp16(bhS + dB0,        bP + k0);
        cp16(bhS + dB0 + 4096, bP + (size_t)64 * CD + k0);
        asm volatile("cp.async.commit_group;" ::: "memory");
    };

    // ---- prologue ----
    ldgA(0);
    cpB(0); cpB(1); cpB(2);
    cvtsts(0);                               // waits on LDG(0) once
    ldgA(1);
    asm volatile("cp.async.wait_group 2;" ::: "memory");   // B(0) arrived
    __syncthreads();

    float acc[2][8][4];
#pragma unroll
    for (int mt = 0; mt < 2; mt++)
#pragma unroll
        for (int nt = 0; nt < 8; nt++)
#pragma unroll
            for (int j = 0; j < 4; j++) acc[mt][nt][j] = 0.f;

#pragma unroll 1
    for (int c = 0; c < 16; c++) {
        if (c + 3 < 16) cpB(c + 3);
        if (c + 1 < 16) {
            cvtsts(c + 1);                   // consumes ra (chunk c+1)
            if (c + 2 < 16) ldgA(c + 2);     // refill ra
        }

        // ---- MMA chunk c ----
        const uint32_t ahS = sbase + SM_AHS + (c & 1) * AH_SZ;
        const uint32_t bhS = sbase + SM_BHS + (c & 3) * BH_SZ;
#pragma unroll
        for (int ks = 0; ks < 2; ks++) {
            uint32_t aH[2][4];
#pragma unroll
            for (int mt = 0; mt < 2; mt++)
                LDSM4(aH[mt], ahS + aoffs[ks] + mt * 1024);
#pragma unroll
            for (int ng = 0; ng < 4; ng++) {
                uint32_t bH[4];
                LDSM4(bH, bhS + boffs[ks] + ng * 1024);
#pragma unroll
                for (int mt = 0; mt < 2; mt++) {
                    MMAH(acc[mt][2 * ng],     aH[mt], bH[0], bH[1]);
                    MMAH(acc[mt][2 * ng + 1], aH[mt], bH[2], bH[3]);
                }
            }
        }

        // B(c+1) must be resident before next iteration's sync
        if (c <= 12)
            asm volatile("cp.async.wait_group 2;" ::: "memory");
        else if (c == 13)
            asm volatile("cp.async.wait_group 1;" ::: "memory");
        else if (c == 14)
            asm volatile("cp.async.wait_group 0;" ::: "memory");
        __syncthreads();
    }

    // ---- epilogue: scores[row] += sum_u tanh(acc + dp[u]) * w2[u] ----
    const int lid4 = lid & 3, lg = lid >> 2;
    const int ulb = wn * 64 + lid4 * 2;
#pragma unroll
    for (int mt = 0; mt < 2; mt++) {
        float s0 = 0.f, s1 = 0.f;
#pragma unroll
        for (int nt = 0; nt < 8; nt++) {
            int ul = ulb + nt * 8;
            float d0 = sdp[ul], d1 = sdp[ul + 1];
            float w0 = sw2[ul], w1 = sw2[ul + 1];
            s0 += fast_tanh(acc[mt][nt][0] + d0) * w0 +
                  fast_tanh(acc[mt][nt][1] + d1) * w1;
            s1 += fast_tanh(acc[mt][nt][2] + d0) * w0 +
                  fast_tanh(acc[mt][nt][3] + d1) * w1;
        }
        s0 += __shfl_xor_sync(0xffffffffu, s0, 1);
        s0 += __shfl_xor_sync(0xffffffffu, s0, 2);
        s1 += __shfl_xor_sync(0xffffffffu, s1, 1);
        s1 += __shfl_xor_sync(0xffffffffu, s1, 2);
        if (lid4 == 0) {
            int r = wm * 32 + mt * 16 + lg;
            atomicAdd(&g_scores[b * CT + t0 + r], s0);
            atomicAdd(&g_scores[b * CT + t0 + r + 8], s1);
        }
    }
}

// -------------------- kernel 2: softmax (+ b2, relu) + zero context --------
__global__ void softmax_kernel(const float* __restrict__ b2, float* __restrict__ out) {
    const int b = blockIdx.x;
    const int tid = threadIdx.x;
    const int wid = tid >> 5, lid = tid & 31;
    __shared__ float wredm[8], wreds[8];
    const float b2v = b2[0];
    float sv[8];

    float mx = 0.f;                        // relu -> scores >= 0
#pragma unroll
    for (int q = 0; q < 8; q++) {
        float s = g_scores[b * CT + q * 256 + tid] + b2v;
        s = s > 0.f ? s : 0.f;
        sv[q] = s;
        mx = fmaxf(mx, s);
    }
#pragma unroll
    for (int off = 16; off >= 1; off >>= 1)
        mx = fmaxf(mx, __shfl_xor_sync(0xffffffffu, mx, off));
    if (lid == 0) wredm[wid] = mx;
    __syncthreads();
    float m = wredm[0];
#pragma unroll
    for (int i = 1; i < 8; i++) m = fmaxf(m, wredm[i]);

    float sum = 0.f;
#pragma unroll
    for (int q = 0; q < 8; q++) {
        float e = expf(sv[q] - m);
        sv[q] = e;
        sum += e;
    }
#pragma unroll
    for (int off = 16; off >= 1; off >>= 1)
        sum += __shfl_xor_sync(0xffffffffu, sum, off);
    if (lid == 0) wreds[wid] = sum;
    __syncthreads();
    float tot = 0.f;
#pragma unroll
    for (int i = 0; i < 8; i++) tot += wreds[i];
    const float inv = 1.f / tot;

    float* attn = out + (size_t)CB * CD + (size_t)b * CT;
#pragma unroll
    for (int q = 0; q < 8; q++) attn[q * 256 + tid] = sv[q] * inv;

    for (int i = tid; i < CD; i += 256) out[b * CD + i] = 0.f;
}

// -------------------- kernel 3: context = sum_t attn * h_enc(fp16) ---------
__global__ __launch_bounds__(256)
void context_kernel(float* __restrict__ out) {
    const int b = blockIdx.y;
    const int t0 = blockIdx.x * 128;
    const int tid = threadIdx.x;
    const int dslot = tid & 63;            // d = dslot*8
    const int grp = tid >> 6;              // rows [grp*32, grp*32+32)
    __shared__ float at[128];
    __shared__ float sred[2][512];
    if (tid < 128) at[tid] = out[(size_t)CB * CD + (size_t)b * CT + t0 + tid];
    __syncthreads();

    const __half* hp = g_Ah + ((size_t)(b * CT + t0 + grp * 32)) * CD + dslot * 8;
    float acc[8];
#pragma unroll
    for (int k = 0; k < 8; k++) acc[k] = 0.f;

#pragma unroll 1
    for (int tt = 0; tt < 32; tt += 8) {
        uint4 hv[8];
#pragma unroll
        for (int j = 0; j < 8; j++)
            hv[j] = *(const uint4*)(hp + (size_t)(tt + j) * CD);
        float a[8];
#pragma unroll
        for (int j = 0; j < 8; j++) a[j] = at[grp * 32 + tt + j];
#pragma unroll
        for (int j = 0; j < 8; j++) {
            float2 f0 = __half22float2(*(__half2*)&hv[j].x);
            float2 f1 = __half22float2(*(__half2*)&hv[j].y);
            float2 f2 = __half22float2(*(__half2*)&hv[j].z);
            float2 f3 = __half22float2(*(__half2*)&hv[j].w);
            acc[0] += a[j] * f0.x;  acc[1] += a[j] * f0.y;
            acc[2] += a[j] * f1.x;  acc[3] += a[j] * f1.y;
            acc[4] += a[j] * f2.x;  acc[5] += a[j] * f2.y;
            acc[6] += a[j] * f3.x;  acc[7] += a[j] * f3.y;
        }
    }

    if (grp >= 2) {
#pragma unroll
        for (int k = 0; k < 8; k++) sred[grp - 2][dslot * 8 + k] = acc[k];
    }
    __syncthreads();
    if (grp < 2) {
#pragma unroll
        for (int k = 0; k < 8; k++) acc[k] += sred[grp][dslot * 8 + k];
    }
    __syncthreads();
    if (grp == 1) {
#pragma unroll
        for (int k = 0; k < 8; k++) sred[0][dslot * 8 + k] = acc[k];
    }
    __syncthreads();
    if (grp == 0) {
        float* cp = out + (size_t)b * CD + dslot * 8;
#pragma unroll
        for (int k = 0; k < 8; k++)
            atomicAdd(cp + k, acc[k] + sred[0][dslot * 8 + k]);
    }
}

// -------------------- host launcher --------------------
extern "C" void kernel_launch(void* const* d_in, const int* in_sizes, int n_in,
                              void* d_out, int out_size) {
    const float* h_enc = (const float*)d_in[0];
    const float* h_dec = (const float*)d_in[1];
    const float* W1    = (const float*)d_in[2];
    const float* b1    = (const float*)d_in[3];
    const float* W2    = (const float*)d_in[4];
    const float* b2    = (const float*)d_in[5];
    float* out = (float*)d_out;

    cudaFuncSetAttribute(score_kernel,
                         cudaFuncAttributeMaxDynamicSharedMemorySize, SM_TOT);

    fused_prep_kernel<<<PREP_GRID, 256>>>(W1, h_dec, b1);
    score_kernel<<<dim3(64, CB), 256, SM_TOT>>>(h_enc, W2);
    softmax_kernel<<<CB, 256>>>(b2, out);
    context_kernel<<<dim3(CT / 128, CB), 256>>>(out);
}

// round 17
// speedup vs baseline: 1.7683x; 1.7683x over previous
#include <cuda_runtime.h>
#include <cuda_fp16.h>
#include <cstdint>

// ---------------------------------------------------------------------------
// pointwise (Bahdanau additive) attention, fp32 via fp16 mma.sync HMMA
// B=32, T=2048, D=512, U=512
// out layout: [0, B*D) = context ; [B*D, B*D + B*T) = attn
// Round 16: revert to the R12 optimum (pre-split A, KC=64 3-stage score,
// 2 CTAs/SM) + evict-first (.cs) hints on the streaming kernels.
// ---------------------------------------------------------------------------

#define CB 32
#define CT 2048
#define CD 512
#define CU 512

// scratch (allocation-free rule: __device__ globals)
__device__ float g_scores[CB * CT];
__device__ float g_dec_proj[CB * CU];
__device__ __half g_W1h[CU * CD];               // transposed: [u][k], fp16
__device__ __half g_Ah[(size_t)CB * CT * CD];   // h_enc rounded to fp16

// -------------------- PTX helpers --------------------
__device__ __forceinline__ uint32_t smem_u32(const void* p) {
    uint32_t a;
    asm("{ .reg .u64 t; cvta.to.shared.u64 t, %1; cvt.u32.u64 %0, t; }"
        : "=r"(a) : "l"(p));
    return a;
}
__device__ __forceinline__ void cp16(uint32_t dst, const void* src) {
    asm volatile("cp.async.cg.shared.global [%0], [%1], 16;"
                 :: "r"(dst), "l"(src) : "memory");
}
__device__ __forceinline__ uint32_t packh2(float a, float b) {
    uint32_t r;                                   // low=a, high=b
    asm("cvt.rn.f16x2.f32 %0, %1, %2;" : "=r"(r) : "f"(b), "f"(a));
    return r;
}
__device__ __forceinline__ float fast_tanh(float x) {
    float e;
    asm("ex2.approx.f32 %0, %1;" : "=f"(e) : "f"(x * 2.885390081777927f)); // e^(2x)
    float r;
    asm("rcp.approx.f32 %0, %1;" : "=f"(r) : "f"(e + 1.0f));
    return fmaf(-2.0f, r, 1.0f);
}

#define LDSM4(r, addr)                                                        \
    asm volatile("ldmatrix.sync.aligned.m8n8.x4.shared.b16 {%0,%1,%2,%3}, [%4];" \
                 : "=r"((r)[0]), "=r"((r)[1]), "=r"((r)[2]), "=r"((r)[3])     \
                 : "r"(addr))

#define MMAH(d, a, b0, b1)                                                    \
    asm volatile("mma.sync.aligned.m16n8k16.row.col.f32.f16.f16.f32 "         \
                 "{%0,%1,%2,%3}, {%4,%5,%6,%7}, {%8,%9}, {%0,%1,%2,%3};"      \
                 : "+f"((d)[0]), "+f"((d)[1]), "+f"((d)[2]), "+f"((d)[3])     \
                 : "r"((a)[0]), "r"((a)[1]), "r"((a)[2]), "r"((a)[3]),        \
                   "r"(b0), "r"(b1))

// -------------------- kernel 0: fused prep --------------------
// blocks [0, 8192): round h_enc to fp16 (16 floats/thread), streaming hints
// blocks [8192, 8448): transpose + round W1_enc
// blocks [8448, 8512): dec projection + zero scores (2 blocks per b)
#define HS_BLOCKS 8192
#define WC_BLOCKS 256
#define PREP_GRID (HS_BLOCKS + WC_BLOCKS + 64)

__global__ __launch_bounds__(256)
void fused_prep_kernel(const float* __restrict__ h,
                       const float* __restrict__ W1,
                       const float* __restrict__ h_dec,
                       const float* __restrict__ b1) {
    const int blk = blockIdx.x;
    const int tid = threadIdx.x;
    __shared__ float sh[32][33];            // w1conv transpose / prep hd

    if (blk < HS_BLOCKS) {
        size_t i = ((size_t)blk * 256 + tid) * 4;     // float4 index
        float4 v0 = __ldcs(((const float4*)h) + i);
        float4 v1 = __ldcs(((const float4*)h) + i + 1);
        float4 v2 = __ldcs(((const float4*)h) + i + 2);
        float4 v3 = __ldcs(((const float4*)h) + i + 3);
        uint4 o0, o1;
        o0.x = packh2(v0.x, v0.y);
        o0.y = packh2(v0.z, v0.w);
        o0.z = packh2(v1.x, v1.y);
        o0.w = packh2(v1.z, v1.w);
        o1.x = packh2(v2.x, v2.y);
        o1.y = packh2(v2.z, v2.w);
        o1.z = packh2(v3.x, v3.y);
        o1.w = packh2(v3.z, v3.w);
        __stcs(((uint4*)g_Ah) + (i >> 1), o0);
        __stcs(((uint4*)g_Ah) + (i >> 1) + 1, o1);
    } else if (blk < HS_BLOCKS + WC_BLOCKS) {
        const int id = blk - HS_BLOCKS;
        const int u0 = (id & 15) * 32, k0 = (id >> 4) * 32;
        const int tx = tid & 31, ty = tid >> 5;
#pragma unroll
        for (int i = 0; i < 4; i++)
            sh[ty + i * 8][tx] = W1[(size_t)(k0 + ty + i * 8) * CU + u0 + tx];
        __syncthreads();
#pragma unroll
        for (int i = 0; i < 4; i++)
            g_W1h[(size_t)(u0 + ty + i * 8) * CD + k0 + tx] =
                __float2half_rn(sh[tx][ty + i * 8]);
    } else {
        const int id = blk - HS_BLOCKS - WC_BLOCKS;
        const int b = id >> 1, uh = id & 1;
        float* hd = &sh[0][0];              // 512 floats
        hd[tid] = h_dec[b * CD + tid];
        hd[tid + 256] = h_dec[b * CD + tid + 256];
        __syncthreads();
        const int u = uh * 256 + tid;
        float a0 = b1[u], a1 = 0.f, a2 = 0.f, a3 = 0.f;
        float a4 = 0.f, a5 = 0.f, a6 = 0.f, a7 = 0.f;
#pragma unroll 4
        for (int k = 0; k < CD; k += 8) {
            a0 += hd[k + 0] * W1[(size_t)(CD + k + 0) * CU + u];
            a1 += hd[k + 1] * W1[(size_t)(CD + k + 1) * CU + u];
            a2 += hd[k + 2] * W1[(size_t)(CD + k + 2) * CU + u];
            a3 += hd[k + 3] * W1[(size_t)(CD + k + 3) * CU + u];
            a4 += hd[k + 4] * W1[(size_t)(CD + k + 4) * CU + u];
            a5 += hd[k + 5] * W1[(size_t)(CD + k + 5) * CU + u];
            a6 += hd[k + 6] * W1[(size_t)(CD + k + 6) * CU + u];
            a7 += hd[k + 7] * W1[(size_t)(CD + k + 7) * CU + u];
        }
        g_dec_proj[b * CU + u] =
            ((a0 + a1) + (a2 + a3)) + ((a4 + a5) + (a6 + a7));
#pragma unroll
        for (int t = uh * 1024 + tid; t < uh * 1024 + 1024; t += 256)
            g_scores[b * CT + t] = 0.f;
    }
}

// -------------------- kernel 1: HMMA fp16 score GEMM --------------------
// CTA tile: 128 t x 128 u, K=512 in 8 chunks of 64. Stage (32KB): Ah | Bh,
// each 128x64 fp16 (16KB), XOR-swizzled 128B rows. 3 stages, 2 CTAs/SM.
#define SM_STAGE 32768
#define SM_BH  16384
#define SM_DP  98304
#define SM_W2  98816
#define SM_TOT 99328

__global__ __launch_bounds__(256, 2)
void score_kernel(const float* __restrict__ W2) {
    extern __shared__ char smem[];
    const uint32_t sbase = smem_u32(smem);
    const int tid = threadIdx.x;
    const int wid = tid >> 5, lid = tid & 31;
    const int wm = wid >> 1, wn = wid & 1;
    const int b = blockIdx.y;
    const int ut = blockIdx.x & 3, tt = blockIdx.x >> 2;  // u-fastest: A L2-hot
    const int t0 = tt * 128, u0 = ut * 128;
    const size_t arow = (size_t)(b * CT + t0);

    // per-lane ldmatrix geometry
    const int rowAf = wm * 32 + (lid & 7) + ((lid >> 3) & 1) * 8;
    const int kselA = lid >> 4;
    const int rowBf = wn * 64 + (lid & 7) + (lid >> 4) * 8;
    const int kselB = (lid >> 3) & 1;
    const int swz = lid & 7;

    // loop-invariant LDSM offsets (relative to stage base)
    uint32_t aoffs[4], boffs[4];
#pragma unroll
    for (int ks = 0; ks < 4; ks++) {
        aoffs[ks] = rowAf * 128 + (((ks * 2 + kselA) ^ swz) << 4);
        boffs[ks] = SM_BH + rowBf * 128 + (((ks * 2 + kselB) ^ swz) << 4);
    }

    // loop-invariant cp.async source pointers + smem dst offsets
    const __half* aptr[4];
    const __half* bptr[4];
    uint32_t doffq[4];
#pragma unroll
    for (int q = 0; q < 4; q++) {
        int idx = q * 256 + tid;
        int row = idx >> 3, ch = idx & 7;
        doffq[q] = row * 128 + ((ch ^ (row & 7)) << 4);
        aptr[q] = g_Ah + (arow + row) * CD + ch * 8;
        bptr[q] = g_W1h + (size_t)(u0 + row) * CD + ch * 8;
    }

    float* sdp = (float*)(smem + SM_DP);
    float* sw2 = (float*)(smem + SM_W2);
    if (tid < 128) {
        sdp[tid] = g_dec_proj[b * CU + u0 + tid];
        sw2[tid] = W2[u0 + tid];
    }

    auto load_chunk = [&](int c) {
        const uint32_t sb = sbase + (c % 3) * SM_STAGE;
        const int kadv = c << 6;            // 64 halves per chunk
#pragma unroll
        for (int q = 0; q < 4; q++) {
            cp16(sb + doffq[q],         aptr[q] + kadv);
            cp16(sb + SM_BH + doffq[q], bptr[q] + kadv);
        }
        asm volatile("cp.async.commit_group;" ::: "memory");
    };

    load_chunk(0);
    load_chunk(1);

    float acc[2][8][4];
#pragma unroll
    for (int mt = 0; mt < 2; mt++)
#pragma unroll
        for (int nt = 0; nt < 8; nt++)
#pragma unroll
            for (int j = 0; j < 4; j++) acc[mt][nt][j] = 0.f;

#pragma unroll 1
    for (int c = 0; c < 8; c++) {
        if (c < 7)
            asm volatile("cp.async.wait_group 1;" ::: "memory");
        else
            asm volatile("cp.async.wait_group 0;" ::: "memory");
        __syncthreads();
        if (c + 2 < 8) load_chunk(c + 2);

        const uint32_t sb = sbase + (c % 3) * SM_STAGE;
#pragma unroll
        for (int ks = 0; ks < 4; ks++) {
            // ---- hoist all fragments for this k16 step ----
            uint32_t aH[2][4], bH[4][4];
#pragma unroll
            for (int mt = 0; mt < 2; mt++)
                LDSM4(aH[mt], sb + aoffs[ks] + mt * 2048);
#pragma unroll
            for (int ng = 0; ng < 4; ng++)
                LDSM4(bH[ng], sb + boffs[ks] + ng * 2048);
            // ---- 16 MMAs, all distinct accumulators ----
#pragma unroll
            for (int ng = 0; ng < 4; ng++)
#pragma unroll
                for (int mt = 0; mt < 2; mt++) {
                    MMAH(acc[mt][2 * ng],     aH[mt], bH[ng][0], bH[ng][1]);
                    MMAH(acc[mt][2 * ng + 1], aH[mt], bH[ng][2], bH[ng][3]);
                }
        }
    }

    // ---- epilogue: scores[row] += sum_u tanh(acc + dp[u]) * w2[u] ----
    const int lid4 = lid & 3, lg = lid >> 2;
    const int ulb = wn * 64 + lid4 * 2;
#pragma unroll
    for (int mt = 0; mt < 2; mt++) {
        float s0 = 0.f, s1 = 0.f;
#pragma unroll
        for (int nt = 0; nt < 8; nt++) {
            int ul = ulb + nt * 8;
            float d0 = sdp[ul], d1 = sdp[ul + 1];
            float w0 = sw2[ul], w1 = sw2[ul + 1];
            s0 += fast_tanh(acc[mt][nt][0] + d0) * w0 +
                  fast_tanh(acc[mt][nt][1] + d1) * w1;
            s1 += fast_tanh(acc[mt][nt][2] + d0) * w0 +
                  fast_tanh(acc[mt][nt][3] + d1) * w1;
        }
        s0 += __shfl_xor_sync(0xffffffffu, s0, 1);
        s0 += __shfl_xor_sync(0xffffffffu, s0, 2);
        s1 += __shfl_xor_sync(0xffffffffu, s1, 1);
        s1 += __shfl_xor_sync(0xffffffffu, s1, 2);
        if (lid4 == 0) {
            int r = wm * 32 + mt * 16 + lg;
            atomicAdd(&g_scores[b * CT + t0 + r], s0);
            atomicAdd(&g_scores[b * CT + t0 + r + 8], s1);
        }
    }
}

// -------------------- kernel 2: softmax (+ b2, relu) + zero context --------
__global__ void softmax_kernel(const float* __restrict__ b2, float* __restrict__ out) {
    const int b = blockIdx.x;
    const int tid = threadIdx.x;
    const int wid = tid >> 5, lid = tid & 31;
    __shared__ float wredm[8], wreds[8];
    const float b2v = b2[0];
    float sv[8];

    float mx = 0.f;                        // relu -> scores >= 0
#pragma unroll
    for (int q = 0; q < 8; q++) {
        float s = g_scores[b * CT + q * 256 + tid] + b2v;
        s = s > 0.f ? s : 0.f;
        sv[q] = s;
        mx = fmaxf(mx, s);
    }
#pragma unroll
    for (int off = 16; off >= 1; off >>= 1)
        mx = fmaxf(mx, __shfl_xor_sync(0xffffffffu, mx, off));
    if (lid == 0) wredm[wid] = mx;
    __syncthreads();
    float m = wredm[0];
#pragma unroll
    for (int i = 1; i < 8; i++) m = fmaxf(m, wredm[i]);

    float sum = 0.f;
#pragma unroll
    for (int q = 0; q < 8; q++) {
        float e = expf(sv[q] - m);
        sv[q] = e;
        sum += e;
    }
#pragma unroll
    for (int off = 16; off >= 1; off >>= 1)
        sum += __shfl_xor_sync(0xffffffffu, sum, off);
    if (lid == 0) wreds[wid] = sum;
    __syncthreads();
    float tot = 0.f;
#pragma unroll
    for (int i = 0; i < 8; i++) tot += wreds[i];
    const float inv = 1.f / tot;

    float* attn = out + (size_t)CB * CD + (size_t)b * CT;
#pragma unroll
    for (int q = 0; q < 8; q++) attn[q * 256 + tid] = sv[q] * inv;

    for (int i = tid; i < CD; i += 256) out[b * CD + i] = 0.f;
}

// -------------------- kernel 3: context = sum_t attn * h_enc(fp16) ---------
// block = 256 threads: 64 d-slots (8 halves each) x 4 row-groups (32 rows).
__global__ __launch_bounds__(256)
void context_kernel(float* __restrict__ out) {
    const int b = blockIdx.y;
    const int t0 = blockIdx.x * 128;
    const int tid = threadIdx.x;
    const int dslot = tid & 63;            // d = dslot*8
    const int grp = tid >> 6;              // rows [grp*32, grp*32+32)
    __shared__ float at[128];
    __shared__ float sred[2][512];
    if (tid < 128) at[tid] = out[(size_t)CB * CD + (size_t)b * CT + t0 + tid];
    __syncthreads();

    const __half* hp = g_Ah + ((size_t)(b * CT + t0 + grp * 32)) * CD + dslot * 8;
    float acc[8];
#pragma unroll
    for (int k = 0; k < 8; k++) acc[k] = 0.f;

#pragma unroll 1
    for (int tt = 0; tt < 32; tt += 8) {
        uint4 hv[8];
#pragma unroll
        for (int j = 0; j < 8; j++)
            hv[j] = __ldcs((const uint4*)(hp + (size_t)(tt + j) * CD));
        float a[8];
#pragma unroll
        for (int j = 0; j < 8; j++) a[j] = at[grp * 32 + tt + j];
#pragma unroll
        for (int j = 0; j < 8; j++) {
            float2 f0 = __half22float2(*(__half2*)&hv[j].x);
            float2 f1 = __half22float2(*(__half2*)&hv[j].y);
            float2 f2 = __half22float2(*(__half2*)&hv[j].z);
            float2 f3 = __half22float2(*(__half2*)&hv[j].w);
            acc[0] += a[j] * f0.x;  acc[1] += a[j] * f0.y;
            acc[2] += a[j] * f1.x;  acc[3] += a[j] * f1.y;
            acc[4] += a[j] * f2.x;  acc[5] += a[j] * f2.y;
            acc[6] += a[j] * f3.x;  acc[7] += a[j] * f3.y;
        }
    }

    if (grp >= 2) {
#pragma unroll
        for (int k = 0; k < 8; k++) sred[grp - 2][dslot * 8 + k] = acc[k];
    }
    __syncthreads();
    if (grp < 2) {
#pragma unroll
        for (int k = 0; k < 8; k++) acc[k] += sred[grp][dslot * 8 + k];
    }
    __syncthreads();
    if (grp == 1) {
#pragma unroll
        for (int k = 0; k < 8; k++) sred[0][dslot * 8 + k] = acc[k];
    }
    __syncthreads();
    if (grp == 0) {
        float* cp = out + (size_t)b * CD + dslot * 8;
#pragma unroll
        for (int k = 0; k < 8; k++)
            atomicAdd(cp + k, acc[k] + sred[0][dslot * 8 + k]);
    }
}

// -------------------- host launcher --------------------
extern "C" void kernel_launch(void* const* d_in, const int* in_sizes, int n_in,
                              void* d_out, int out_size) {
    const float* h_enc = (const float*)d_in[0];
    const float* h_dec = (const float*)d_in[1];
    const float* W1    = (const float*)d_in[2];
    const float* b1    = (const float*)d_in[3];
    const float* W2    = (const float*)d_in[4];
    const float* b2    = (const float*)d_in[5];
    float* out = (float*)d_out;

    cudaFuncSetAttribute(score_kernel,
                         cudaFuncAttributeMaxDynamicSharedMemorySize, SM_TOT);

    fused_prep_kernel<<<PREP_GRID, 256>>>(h_enc, W1, h_dec, b1);
    score_kernel<<<dim3(64, CB), 256, SM_TOT>>>(W2);
    softmax_kernel<<<CB, 256>>>(b2, out);
    context_kernel<<<dim3(CT / 128, CB), 256>>>(out);
}